// round 1
// baseline (speedup 1.0000x reference)
#include <cuda_runtime.h>

#define IN_SZ  448
#define OUT_SZ 224
#define BATCH  64

// Scratch: 1D separable masks + per-image crop params (device globals: allocation-free)
__device__ float  g_mrow[BATCH * IN_SZ];
__device__ float  g_mcol[BATCH * IN_SZ];
__device__ float4 g_params[BATCH];   // (w_off, w_end, h_off, h_end)

__device__ __forceinline__ float sig10(float z) {
    return 1.0f / (1.0f + __expf(-10.0f * z));
}

// ---------------------------------------------------------------------------
// Kernel 1: per-image params + 1D sigmoid masks. grid=64, block=448. Tiny.
// ---------------------------------------------------------------------------
__global__ void racnn_mask_kernel(const float* __restrict__ locs) {
    const int b = blockIdx.x;
    const int i = threadIdx.x;            // 0..447

    float tx = locs[b * 3 + 0];
    float ty = locs[b * 3 + 1];
    float tl = locs[b * 3 + 2];

    tl = fmaxf(tl, 448.0f / 3.0f);
    tx = fminf(fmaxf(tx, tl), 448.0f - tl);
    ty = fminf(fmaxf(ty, tl), 448.0f - tl);

    const float w_off = fmaxf(floorf(tx - tl), 0.0f);
    const float h_off = fmaxf(floorf(ty - tl), 0.0f);
    const float w_end = fminf(floorf(tx + tl), 448.0f);
    const float h_end = fminf(floorf(ty + tl), 448.0f);

    const float fi = (float)i;
    g_mrow[b * IN_SZ + i] = sig10(fi - w_off) - sig10(fi - w_end);
    g_mcol[b * IN_SZ + i] = sig10(fi - h_off) - sig10(fi - h_end);

    if (i == 0) g_params[b] = make_float4(w_off, w_end, h_off, h_end);
}

// ---------------------------------------------------------------------------
// Kernel 2: fused mask + bilinear gather.
// block = (224, 2): 224 output cols x 2 output rows = 448 threads (14 warps).
// grid  = (112 row-pairs, 3 channels, 64 images); x-fastest ordering keeps
// consecutive source rows of the same (b,ch) hot in L2.
// ---------------------------------------------------------------------------
__global__ __launch_bounds__(448) void racnn_resize_kernel(
    const float* __restrict__ img, float* __restrict__ out)
{
    const int b  = blockIdx.z;
    const int ch = blockIdx.y;
    const int jr = blockIdx.x * 2 + threadIdx.y;
    const int jc = threadIdx.x;

    const float4 p = g_params[b];
    const float w_off = p.x, w_end = p.y, h_off = p.z, h_end = p.w;

    // Row sampling (uniform across threadIdx.x)
    const float step_r = (w_end - w_off - 1.0f) * (1.0f / 223.0f);
    const float src_r  = w_off + (float)jr * step_r;
    const float r0f    = fminf(fmaxf(floorf(src_r), 0.0f), 447.0f);
    const float wr     = src_r - r0f;
    const int   r0     = (int)r0f;
    const int   r1     = min(r0 + 1, IN_SZ - 1);

    // Column sampling (per-thread)
    const float step_c = (h_end - h_off - 1.0f) * (1.0f / 223.0f);
    const float src_c  = h_off + (float)jc * step_c;
    const float c0f    = fminf(fmaxf(floorf(src_c), 0.0f), 447.0f);
    const float wc     = src_c - c0f;
    const int   c0     = (int)c0f;
    const int   c1     = min(c0 + 1, IN_SZ - 1);

    // Precomputed 1D mask values (L1-broadcast for rows, cached for cols)
    const float mr0 = __ldg(&g_mrow[b * IN_SZ + r0]);
    const float mr1 = __ldg(&g_mrow[b * IN_SZ + r1]);
    const float mc0 = __ldg(&g_mcol[b * IN_SZ + c0]);
    const float mc1 = __ldg(&g_mcol[b * IN_SZ + c1]);

    const float* base = img + (size_t)(b * 3 + ch) * (IN_SZ * IN_SZ);
    const float x00 = __ldg(base + r0 * IN_SZ + c0) * mr0 * mc0;
    const float x01 = __ldg(base + r0 * IN_SZ + c1) * mr0 * mc1;
    const float x10 = __ldg(base + r1 * IN_SZ + c0) * mr1 * mc0;
    const float x11 = __ldg(base + r1 * IN_SZ + c1) * mr1 * mc1;

    const float top = (1.0f - wc) * x00 + wc * x01;
    const float bot = (1.0f - wc) * x10 + wc * x11;
    const float res = (1.0f - wr) * top + wr * bot;

    out[((size_t)(b * 3 + ch) * OUT_SZ + jr) * OUT_SZ + jc] = res;
}

// ---------------------------------------------------------------------------
extern "C" void kernel_launch(void* const* d_in, const int* in_sizes, int n_in,
                              void* d_out, int out_size)
{
    // Robust input identification by element count:
    // images = 64*3*448*448 = 38,535,168 ; locs = 64*3 = 192
    const float* images = (const float*)d_in[0];
    const float* locs   = (const float*)d_in[1];
    if (n_in >= 2 && in_sizes[0] == BATCH * 3) {  // swapped order
        locs   = (const float*)d_in[0];
        images = (const float*)d_in[1];
    }
    float* out = (float*)d_out;

    racnn_mask_kernel<<<BATCH, IN_SZ>>>(locs);

    dim3 block(OUT_SZ, 2, 1);        // 448 threads
    dim3 grid(OUT_SZ / 2, 3, BATCH); // (112, 3, 64)
    racnn_resize_kernel<<<grid, block>>>(images, out);
}

// round 2
// speedup vs baseline: 1.5937x; 1.5937x over previous
#include <cuda_runtime.h>

#define IN_SZ  448
#define OUT_SZ 224
#define BATCH  64

// Precomputed per-output-row / per-output-column bilinear+mask coefficients.
// col side: a = (a0, a1), cidx = (c0, c1)
// row side: bb = (b0, b1), ridx = (r0, r1)
__device__ float2 g_a[BATCH * OUT_SZ];
__device__ int2   g_c[BATCH * OUT_SZ];
__device__ float2 g_b[BATCH * OUT_SZ];
__device__ int2   g_r[BATCH * OUT_SZ];

__device__ __forceinline__ float sig10(float z) {
    return 1.0f / (1.0f + __expf(-10.0f * z));
}

// ---------------------------------------------------------------------------
// Prologue: per-(image, output-index) coefficients. grid=64, block=224. Tiny.
// ---------------------------------------------------------------------------
__global__ void racnn_coef_kernel(const float* __restrict__ locs) {
    const int b = blockIdx.x;
    const int j = threadIdx.x;            // 0..223

    float tx = locs[b * 3 + 0];
    float ty = locs[b * 3 + 1];
    float tl = locs[b * 3 + 2];

    tl = fmaxf(tl, 448.0f / 3.0f);
    tx = fminf(fmaxf(tx, tl), 448.0f - tl);
    ty = fminf(fmaxf(ty, tl), 448.0f - tl);

    const float w_off = fmaxf(floorf(tx - tl), 0.0f);
    const float h_off = fmaxf(floorf(ty - tl), 0.0f);
    const float w_end = fminf(floorf(tx + tl), 448.0f);
    const float h_end = fminf(floorf(ty + tl), 448.0f);

    const float fj = (float)j;

    // ---- row side (r axis uses w_off/w_end, matches reference) ----
    {
        const float step  = (w_end - w_off - 1.0f) * (1.0f / 223.0f);
        const float src   = w_off + fj * step;
        const float r0f   = fminf(fmaxf(floorf(src), 0.0f), 447.0f);
        const float wr    = src - r0f;
        const int   r0    = (int)r0f;
        const int   r1    = min(r0 + 1, IN_SZ - 1);
        const float mr0   = sig10(r0f - w_off) - sig10(r0f - w_end);
        const float r1f   = (float)r1;
        const float mr1   = sig10(r1f - w_off) - sig10(r1f - w_end);
        g_b[b * OUT_SZ + j] = make_float2((1.0f - wr) * mr0, wr * mr1);
        g_r[b * OUT_SZ + j] = make_int2(r0, r1);
    }

    // ---- column side (c axis uses h_off/h_end) ----
    {
        const float step  = (h_end - h_off - 1.0f) * (1.0f / 223.0f);
        const float src   = h_off + fj * step;
        const float c0f   = fminf(fmaxf(floorf(src), 0.0f), 447.0f);
        const float wc    = src - c0f;
        const int   c0    = (int)c0f;
        const int   c1    = min(c0 + 1, IN_SZ - 1);
        const float mc0   = sig10(c0f - h_off) - sig10(c0f - h_end);
        const float c1f   = (float)c1;
        const float mc1   = sig10(c1f - h_off) - sig10(c1f - h_end);
        g_a[b * OUT_SZ + j] = make_float2((1.0f - wc) * mc0, wc * mc1);
        g_c[b * OUT_SZ + j] = make_int2(c0, c1);
    }
}

// ---------------------------------------------------------------------------
// Main: pure gather + 6 FMA per pixel. Each thread: 1 column x 4 output rows.
// block (224, 2) = 448 threads covering 8 output rows; grid (28, 3, 64).
// ---------------------------------------------------------------------------
__global__ __launch_bounds__(448) void racnn_resize_kernel(
    const float* __restrict__ img, float* __restrict__ out)
{
    const int b  = blockIdx.z;
    const int ch = blockIdx.y;
    const int jc = threadIdx.x;
    const int jr_base = blockIdx.x * 8 + threadIdx.y * 4;

    // Per-thread column coefficients (coalesced loads, once)
    const float2 a = __ldg(&g_a[b * OUT_SZ + jc]);
    const int2   c = __ldg(&g_c[b * OUT_SZ + jc]);

    const float* base = img + (size_t)(b * 3 + ch) * (IN_SZ * IN_SZ);

    float  v00[4], v01[4], v10[4], v11[4];
    float2 bb[4];

    #pragma unroll
    for (int k = 0; k < 4; k++) {
        const int jr = jr_base + k;
        const int2   r  = __ldg(&g_r[b * OUT_SZ + jr]);   // warp-uniform
        bb[k]           = __ldg(&g_b[b * OUT_SZ + jr]);   // warp-uniform
        const float* row0 = base + r.x * IN_SZ;
        const float* row1 = base + r.y * IN_SZ;
        v00[k] = __ldg(row0 + c.x);
        v01[k] = __ldg(row0 + c.y);
        v10[k] = __ldg(row1 + c.x);
        v11[k] = __ldg(row1 + c.y);
    }

    float* orow = out + ((size_t)(b * 3 + ch) * OUT_SZ + jr_base) * OUT_SZ + jc;

    #pragma unroll
    for (int k = 0; k < 4; k++) {
        const float top = fmaf(a.y, v01[k], a.x * v00[k]);
        const float bot = fmaf(a.y, v11[k], a.x * v10[k]);
        orow[k * OUT_SZ] = fmaf(bb[k].y, bot, bb[k].x * top);
    }
}

// ---------------------------------------------------------------------------
extern "C" void kernel_launch(void* const* d_in, const int* in_sizes, int n_in,
                              void* d_out, int out_size)
{
    // images = 64*3*448*448 elements ; locs = 192 elements
    const float* images = (const float*)d_in[0];
    const float* locs   = (const float*)d_in[1];
    if (n_in >= 2 && in_sizes[0] == BATCH * 3) {
        locs   = (const float*)d_in[0];
        images = (const float*)d_in[1];
    }
    float* out = (float*)d_out;

    racnn_coef_kernel<<<BATCH, OUT_SZ>>>(locs);

    dim3 block(OUT_SZ, 2, 1);            // 448 threads
    dim3 grid(OUT_SZ / 8, 3, BATCH);     // (28, 3, 64)
    racnn_resize_kernel<<<grid, block>>>(images, out);
}